// round 4
// baseline (speedup 1.0000x reference)
#include <cuda_runtime.h>
#include <cstdint>

// ---------------------------------------------------------------------------
// SuperLoss fused single-kernel:
//   phase A: blocks 0..7 fill the W0 LUT; all blocks partial-sum their
//            grid-stride slice of the input.
//   grid barrier (atomic counter spin; grid sized to guaranteed residency)
//   phase B: every block redundantly computes tau (deterministic, identical),
//            then maps ITS OWN slice (same addresses as phase A -> L2-hot),
//            writing with __stcs (evict-first) so stores don't thrash L2.
//
// Math:  u = max(0, 1 + C*(l-tau)), C = e/(2*lam)
//        unclamped: out = lam*w*(w+2), w = W0 via float2 LUT (w0, slope)
//                   indexed by float exponent/mantissa bits of u
//        clamped:   out = e*(l-tau) + lam
// Zero MUFU in the hot loop.
// ---------------------------------------------------------------------------

#define C_SLOPE   13.591409142295225f   // e / (2*0.1)
#define INV_E     0.36787944117144233f
#define E_CONST   2.718281828459045f
#define LAMF      0.1f
#define U_MIN     3.725290298461914e-9f // 2^-28
#define U_MAXC    15.999999f
#define IDX_OFF   6336                  // (127-28) << 6
#define LUT_N     2048                  // 32 octaves * 64 cells
#define T_INV     7.62939453125e-6f     // 1/2^17
#define NTHREADS  256
#define MAX_GRID  4096

__device__ float2   g_lut[LUT_N];
__device__ float    g_partial[MAX_GRID];
__device__ unsigned g_arrive = 0;
__device__ unsigned g_exit   = 0;

// ---------------------------------------------------------------------------
// Accurate W0 from u = e*y + 1 (reference's fp32 Halley scheme) — LUT nodes only
// ---------------------------------------------------------------------------
__device__ __forceinline__ float w0_from_u(float u)
{
    float p  = sqrtf(fmaxf(2.0f * u, 0.0f));
    float wb = -1.0f + p - p * p * (1.0f / 3.0f) + (11.0f / 72.0f) * p * p * p;
    float y  = (u - 1.0f) * INV_E;
    float w  = (y < 0.0f) ? wb : log1pf(y);
#pragma unroll
    for (int it = 0; it < 8; ++it) {
        float ew   = expf(w);
        float f    = fmaf(w, ew, -y);
        float wp1  = w + 1.0f;
        float safe = (fabsf(wp1) < 1e-6f) ? 1e-6f : wp1;
        float den  = ew * wp1 - (w + 2.0f) * f / (2.0f * safe);
        den        = (fabsf(den) < 1e-12f) ? 1e-12f : den;
        w          = w - f / den;
    }
    return w;
}

__device__ __forceinline__ float superloss_elem(float l, float tau,
                                                const float2* __restrict__ slut)
{
    float d = l - tau;
    float u = fmaf(C_SLOPE, d, 1.0f);
    float out_c = fmaf(E_CONST, d, LAMF);                // clamp branch
    if (u < U_MIN) return out_c;
    float uc = fminf(u, U_MAXC);
    unsigned ub = __float_as_uint(uc);
    int   idx = (int)(ub >> 17) - IDX_OFF;
    float t   = (float)(int)(ub & 0x1FFFFu);
    float2 e  = slut[idx];
    float w   = fmaf(t, e.y, e.x);
    float lw  = LAMF * w;
    return fmaf(lw, w, lw + lw);                         // lam*w*(w+2)
}

// ---------------------------------------------------------------------------
__global__ void __launch_bounds__(NTHREADS)
fused_kernel(const float* __restrict__ in, float* __restrict__ out, int n)
{
    __shared__ float2 slut[LUT_N];                       // 16 KB
    __shared__ float  ws[NTHREADS / 32];
    __shared__ double wd[NTHREADS / 32];
    __shared__ float  s_tau;

    const int tid    = blockIdx.x * NTHREADS + threadIdx.x;
    const int stride = gridDim.x * NTHREADS;
    const int n4     = n >> 2;
    const float4* in4 = reinterpret_cast<const float4*>(in);

    // ---- phase A0: LUT fill (blocks 0..7, one Halley eval per thread) ----
    if (blockIdx.x < LUT_N / NTHREADS) {
        int e = blockIdx.x * NTHREADS + threadIdx.x;
        int oct = e >> 6;
        int j   = e & 63;
        unsigned bits = ((unsigned)(oct + 99) << 23) | ((unsigned)j << 17);
        float u0 = __uint_as_float(bits);
        float u1 = __uint_as_float(bits + 0x20000u);
        float w0 = w0_from_u(u0);
        float w1 = w0_from_u(u1);
        g_lut[e] = make_float2(w0, (w1 - w0) * T_INV);
    }

    // ---- phase A1: partial sum over this block's grid-stride slice ----
    float s0 = 0.0f, s1 = 0.0f, s2 = 0.0f, s3 = 0.0f;
    int i = tid;
    for (; i + 3 * stride < n4; i += 4 * stride) {
        float4 a = in4[i];
        float4 b = in4[i + stride];
        float4 c = in4[i + 2 * stride];
        float4 d = in4[i + 3 * stride];
        s0 += (a.x + a.y) + (a.z + a.w);
        s1 += (b.x + b.y) + (b.z + b.w);
        s2 += (c.x + c.y) + (c.z + c.w);
        s3 += (d.x + d.y) + (d.z + d.w);
    }
    for (; i < n4; i += stride) {
        float4 a = in4[i];
        s0 += (a.x + a.y) + (a.z + a.w);
    }
    for (int k = (n4 << 2) + tid; k < n; k += stride)
        s0 += in[k];
    float sum = (s0 + s1) + (s2 + s3);

#pragma unroll
    for (int o = 16; o > 0; o >>= 1)
        sum += __shfl_xor_sync(0xFFFFFFFFu, sum, o);
    if ((threadIdx.x & 31) == 0) ws[threadIdx.x >> 5] = sum;
    __syncthreads();
    if (threadIdx.x == 0) {
        float s = ws[0];
#pragma unroll
        for (int w = 1; w < NTHREADS / 32; ++w) s += ws[w];
        g_partial[blockIdx.x] = s;
    }

    // ---- grid barrier (all blocks guaranteed resident by launch sizing) ----
    __threadfence();                       // publish g_partial + g_lut
    __syncthreads();
    if (threadIdx.x == 0) {
        atomicAdd(&g_arrive, 1u);
        volatile unsigned* p = &g_arrive;
        while (*p < gridDim.x) __nanosleep(64);
    }
    __syncthreads();
    __threadfence();

    // ---- phase B0: LUT -> shared; redundant deterministic tau per block ----
    {
        const float4* src = reinterpret_cast<const float4*>(g_lut);
        float4* dst = reinterpret_cast<float4*>(slut);
        for (int k = threadIdx.x; k < LUT_N / 2; k += NTHREADS)
            dst[k] = src[k];
    }
    {
        double acc = 0.0;
        for (int k = threadIdx.x; k < (int)gridDim.x; k += NTHREADS)
            acc += (double)g_partial[k];
#pragma unroll
        for (int o = 16; o > 0; o >>= 1)
            acc += __shfl_xor_sync(0xFFFFFFFFu, acc, o);
        if ((threadIdx.x & 31) == 0) wd[threadIdx.x >> 5] = acc;
        __syncthreads();
        if (threadIdx.x == 0) {
            double t = wd[0];
#pragma unroll
            for (int w = 1; w < NTHREADS / 32; ++w) t += wd[w];
            s_tau = (float)(t / (double)n);
        }
    }
    __syncthreads();
    const float tau = s_tau;

    // ---- phase B1: map the SAME slice (L2-hot), streaming stores ----
    float4* out4 = reinterpret_cast<float4*>(out);
    int j = tid;
    for (; j + stride < n4; j += 2 * stride) {
        float4 v0 = in4[j];
        float4 v1 = in4[j + stride];
        float4 r0, r1;
        r0.x = superloss_elem(v0.x, tau, slut);
        r0.y = superloss_elem(v0.y, tau, slut);
        r0.z = superloss_elem(v0.z, tau, slut);
        r0.w = superloss_elem(v0.w, tau, slut);
        r1.x = superloss_elem(v1.x, tau, slut);
        r1.y = superloss_elem(v1.y, tau, slut);
        r1.z = superloss_elem(v1.z, tau, slut);
        r1.w = superloss_elem(v1.w, tau, slut);
        __stcs(&out4[j], r0);
        __stcs(&out4[j + stride], r1);
    }
    for (; j < n4; j += stride) {
        float4 v = in4[j];
        float4 r;
        r.x = superloss_elem(v.x, tau, slut);
        r.y = superloss_elem(v.y, tau, slut);
        r.z = superloss_elem(v.z, tau, slut);
        r.w = superloss_elem(v.w, tau, slut);
        __stcs(&out4[j], r);
    }
    for (int k = (n4 << 2) + tid; k < n; k += stride)
        __stcs(&out[k], superloss_elem(in[k], tau, slut));

    // ---- exit protocol: last block resets counters for the next replay ----
    __syncthreads();
    if (threadIdx.x == 0) {
        unsigned t = atomicAdd(&g_exit, 1u);
        if (t == gridDim.x - 1) {          // everyone has passed the spin
            g_arrive = 0;
            g_exit   = 0;
            __threadfence();
        }
    }
}

// ---------------------------------------------------------------------------
extern "C" void kernel_launch(void* const* d_in, const int* in_sizes, int n_in,
                              void* d_out, int out_size)
{
    const float* loss = (const float*)d_in[0];
    float*       out  = (float*)d_out;
    int n = in_sizes[0];

    int dev = 0, sms = 0, occ = 0;
    cudaGetDevice(&dev);
    cudaDeviceGetAttribute(&sms, cudaDevAttrMultiProcessorCount, dev);
    cudaOccupancyMaxActiveBlocksPerMultiprocessor(&occ, fused_kernel, NTHREADS, 0);
    if (occ < 1) occ = 1;
    long grid_l = (long)sms * (long)occ;
    if (grid_l > MAX_GRID) grid_l = MAX_GRID;
    int grid = (int)grid_l;
    if (grid < LUT_N / NTHREADS) grid = LUT_N / NTHREADS;  // >= 8 for LUT fill

    fused_kernel<<<grid, NTHREADS>>>(loss, out, n);
}

// round 5
// speedup vs baseline: 1.2466x; 1.2466x over previous
#include <cuda_runtime.h>
#include <cstdint>

// ---------------------------------------------------------------------------
// SuperLoss, two-kernel:
//  K1 (reduce_prep): grid-stride partial sums (4-way MLP) + last-block tau
//     (double, deterministic) + 8 trailing blocks fill the W0 LUT.
//  K2 (map): out = lam*w*(w+2) off-clamp (w via float2 LUT over
//     u = 1 + C*(l-tau), float-exponent-indexed geometric grid, LDS.64),
//     out = e*(l-tau) + lam on the clamp. Descending 4-band walk with 4-way
//     MLP; __stcs streaming stores. Zero MUFU anywhere in the hot loops.
// ---------------------------------------------------------------------------

#define C_SLOPE   13.591409142295225f   // e / (2*0.1)
#define INV_E     0.36787944117144233f
#define E_CONST   2.718281828459045f
#define LAMF      0.1f
#define U_MIN     3.725290298461914e-9f // 2^-28
#define U_MAXC    15.999999f
#define IDX_OFF   6336                  // (127-28) << 6
#define LUT_N     2048                  // 32 octaves * 64 cells
#define T_INV     7.62939453125e-6f     // 1/2^17
#define NT        256
#define LUT_BLOCKS 8
#define MAX_GRID  4096

__device__ float2   g_lut[LUT_N];
__device__ float    g_partial[MAX_GRID];
__device__ float    g_tau;
__device__ unsigned g_ctr = 0;

// ---------------------------------------------------------------------------
__device__ __forceinline__ float w0_from_u(float u)   // LUT nodes only
{
    float p  = sqrtf(fmaxf(2.0f * u, 0.0f));
    float wb = -1.0f + p - p * p * (1.0f / 3.0f) + (11.0f / 72.0f) * p * p * p;
    float y  = (u - 1.0f) * INV_E;
    float w  = (y < 0.0f) ? wb : log1pf(y);
#pragma unroll
    for (int it = 0; it < 8; ++it) {
        float ew   = expf(w);
        float f    = fmaf(w, ew, -y);
        float wp1  = w + 1.0f;
        float safe = (fabsf(wp1) < 1e-6f) ? 1e-6f : wp1;
        float den  = ew * wp1 - (w + 2.0f) * f / (2.0f * safe);
        den        = (fabsf(den) < 1e-12f) ? 1e-12f : den;
        w          = w - f / den;
    }
    return w;
}

// ---------------------------------------------------------------------------
// K1: partial sums + LUT fill + last-block tau
// ---------------------------------------------------------------------------
__global__ void __launch_bounds__(NT)
reduce_prep_kernel(const float* __restrict__ in, int n)
{
    const int rblocks = gridDim.x - LUT_BLOCKS;

    if (blockIdx.x >= rblocks) {                        // LUT blocks
        int e = (blockIdx.x - rblocks) * NT + threadIdx.x;
        if (e < LUT_N) {
            int oct = e >> 6;
            int j   = e & 63;
            unsigned bits = ((unsigned)(oct + 99) << 23) | ((unsigned)j << 17);
            float u0 = __uint_as_float(bits);
            float u1 = __uint_as_float(bits + 0x20000u);
            float w0 = w0_from_u(u0);
            float w1 = w0_from_u(u1);
            g_lut[e] = make_float2(w0, (w1 - w0) * T_INV);
        }
        return;
    }

    const int tid    = blockIdx.x * NT + threadIdx.x;
    const int stride = rblocks * NT;
    const int n4     = n >> 2;
    const float4* in4 = reinterpret_cast<const float4*>(in);

    float s0 = 0.0f, s1 = 0.0f, s2 = 0.0f, s3 = 0.0f;
    int i = tid;
    for (; i + 3 * stride < n4; i += 4 * stride) {
        float4 a = in4[i];
        float4 b = in4[i + stride];
        float4 c = in4[i + 2 * stride];
        float4 d = in4[i + 3 * stride];
        s0 += (a.x + a.y) + (a.z + a.w);
        s1 += (b.x + b.y) + (b.z + b.w);
        s2 += (c.x + c.y) + (c.z + c.w);
        s3 += (d.x + d.y) + (d.z + d.w);
    }
    for (; i < n4; i += stride) {
        float4 a = in4[i];
        s0 += (a.x + a.y) + (a.z + a.w);
    }
    for (int k = (n4 << 2) + tid; k < n; k += stride)
        s0 += in[k];
    float sum = (s0 + s1) + (s2 + s3);

#pragma unroll
    for (int o = 16; o > 0; o >>= 1)
        sum += __shfl_xor_sync(0xFFFFFFFFu, sum, o);

    __shared__ float ws[NT / 32];
    if ((threadIdx.x & 31) == 0) ws[threadIdx.x >> 5] = sum;
    __syncthreads();
    if (threadIdx.x == 0) {
        float s = ws[0];
#pragma unroll
        for (int w = 1; w < NT / 32; ++w) s += ws[w];
        g_partial[blockIdx.x] = s;
    }

    __shared__ bool s_last;
    __threadfence();
    if (threadIdx.x == 0) {
        unsigned t = atomicAdd(&g_ctr, 1u);
        s_last = (t == (unsigned)(rblocks - 1));
    }
    __syncthreads();
    if (s_last) {
        double acc = 0.0;
        for (int k = threadIdx.x; k < rblocks; k += NT)
            acc += (double)g_partial[k];
#pragma unroll
        for (int o = 16; o > 0; o >>= 1)
            acc += __shfl_xor_sync(0xFFFFFFFFu, acc, o);
        __shared__ double wd[NT / 32];
        if ((threadIdx.x & 31) == 0) wd[threadIdx.x >> 5] = acc;
        __syncthreads();
        if (threadIdx.x == 0) {
            double t = wd[0];
#pragma unroll
            for (int w = 1; w < NT / 32; ++w) t += wd[w];
            g_tau = (float)(t / (double)n);
            g_ctr = 0;                                   // reset for next replay
        }
    }
}

// ---------------------------------------------------------------------------
// K2: map. out = lam*w*(w+2) | e*d + lam. 4-way MLP, descending bands.
// ---------------------------------------------------------------------------
__device__ __forceinline__ float superloss_elem(float l, float tau,
                                                const float2* __restrict__ slut)
{
    float d = l - tau;
    float u = fmaf(C_SLOPE, d, 1.0f);
    float out_c = fmaf(E_CONST, d, LAMF);                // clamp branch
    if (u < U_MIN) return out_c;
    float uc = fminf(u, U_MAXC);
    unsigned ub = __float_as_uint(uc);
    int   idx = (int)(ub >> 17) - IDX_OFF;
    float t   = (float)(int)(ub & 0x1FFFFu);
    float2 e  = slut[idx];
    float w   = fmaf(t, e.y, e.x);
    float lw  = LAMF * w;
    return fmaf(lw, w, lw + lw);                         // lam*w*(w+2)
}

__device__ __forceinline__ float4 superloss_vec4(float4 v, float tau,
                                                 const float2* __restrict__ slut)
{
    float4 r;
    r.x = superloss_elem(v.x, tau, slut);
    r.y = superloss_elem(v.y, tau, slut);
    r.z = superloss_elem(v.z, tau, slut);
    r.w = superloss_elem(v.w, tau, slut);
    return r;
}

__global__ void __launch_bounds__(NT)
map_kernel(const float* __restrict__ in, float* __restrict__ out, int n)
{
    __shared__ float2 slut[LUT_N];                       // 16 KB
    {
        const float4* src = reinterpret_cast<const float4*>(g_lut);
        float4* dst = reinterpret_cast<float4*>(slut);
        for (int k = threadIdx.x; k < LUT_N / 2; k += NT)
            dst[k] = src[k];
    }
    __syncthreads();

    const float tau = g_tau;

    const int tid    = blockIdx.x * NT + threadIdx.x;
    const int stride = gridDim.x * NT;
    const int n4     = n >> 2;
    const float4* in4  = reinterpret_cast<const float4*>(in);
    float4*       out4 = reinterpret_cast<float4*>(out);

    // Descending bands (anti-cyclic vs. reduce's ascending stream), 4-way MLP.
    int i = tid;
    for (; i + 3 * stride < n4; i += 4 * stride) {
        int j0 = n4 - 1 - i;
        int j1 = j0 - stride;
        int j2 = j0 - 2 * stride;
        int j3 = j0 - 3 * stride;
        float4 v0 = in4[j0];
        float4 v1 = in4[j1];
        float4 v2 = in4[j2];
        float4 v3 = in4[j3];
        float4 r0 = superloss_vec4(v0, tau, slut);
        float4 r1 = superloss_vec4(v1, tau, slut);
        float4 r2 = superloss_vec4(v2, tau, slut);
        float4 r3 = superloss_vec4(v3, tau, slut);
        __stcs(&out4[j0], r0);
        __stcs(&out4[j1], r1);
        __stcs(&out4[j2], r2);
        __stcs(&out4[j3], r3);
    }
    for (; i < n4; i += stride) {
        int j = n4 - 1 - i;
        float4 v = in4[j];
        __stcs(&out4[j], superloss_vec4(v, tau, slut));
    }
    for (int k = (n4 << 2) + tid; k < n; k += stride)
        __stcs(&out[k], superloss_elem(in[k], tau, slut));
}

// ---------------------------------------------------------------------------
extern "C" void kernel_launch(void* const* d_in, const int* in_sizes, int n_in,
                              void* d_out, int out_size)
{
    const float* loss = (const float*)d_in[0];
    float*       out  = (float*)d_out;
    int n = in_sizes[0];

    int dev = 0, sms = 148;
    cudaGetDevice(&dev);
    cudaDeviceGetAttribute(&sms, cudaDevAttrMultiProcessorCount, dev);

    int rgrid = sms * 8;                                 // uniform 8 blocks/SM
    if (rgrid > MAX_GRID - LUT_BLOCKS) rgrid = MAX_GRID - LUT_BLOCKS;

    int mocc = 0;
    cudaOccupancyMaxActiveBlocksPerMultiprocessor(&mocc, map_kernel, NT, 0);
    if (mocc < 1) mocc = 1;
    int mgrid = sms * mocc;
    if (mgrid > MAX_GRID) mgrid = MAX_GRID;

    reduce_prep_kernel<<<rgrid + LUT_BLOCKS, NT>>>(loss, n);
    map_kernel<<<mgrid, NT>>>(loss, out, n);
}